// round 6
// baseline (speedup 1.0000x reference)
#include <cuda_runtime.h>
#include <cuda_bf16.h>
#include <cstdint>

#define BB    64
#define NNODE 1024
#define IND   512
#define HIDD  1024
#define LATD  256
#define TOK   (BB * NNODE)   // 65536

// ---------------------------------------------------------------------------
// Scratch (device globals — allocation is forbidden)
// ---------------------------------------------------------------------------
__device__ float g_d[TOK];
__device__ __align__(16) __nv_bfloat16 g_ahi[(size_t)BB * NNODE * NNODE];
__device__ __align__(16) __nv_bfloat16 g_alo[(size_t)BB * NNODE * NNODE];
__device__ __align__(16) __nv_bfloat16 g_xthi[(size_t)BB * IND * NNODE];
__device__ __align__(16) __nv_bfloat16 g_xtlo[(size_t)BB * IND * NNODE];
__device__ __align__(16) __nv_bfloat16 g_hhi[(size_t)TOK * IND];
__device__ __align__(16) __nv_bfloat16 g_hlo[(size_t)TOK * IND];
__device__ __align__(16) __nv_bfloat16 g_h1hi[(size_t)TOK * HIDD];
__device__ __align__(16) __nv_bfloat16 g_h1lo[(size_t)TOK * HIDD];
__device__ __align__(16) __nv_bfloat16 g_w1hi[HIDD * IND],  g_w1lo[HIDD * IND];
__device__ __align__(16) __nv_bfloat16 g_wcathi[2 * LATD * HIDD];   // [Wmu; Wlv]
__device__ __align__(16) __nv_bfloat16 g_wcatlo[2 * LATD * HIDD];

// ---------------------------------------------------------------------------
// helpers (baseline PTX only)
// ---------------------------------------------------------------------------
__device__ __forceinline__ uint32_t smem_u32(const void* p) {
    uint32_t a;
    asm("{ .reg .u64 t; cvta.to.shared.u64 t, %1; cvt.u32.u64 %0, t; }" : "=r"(a) : "l"(p));
    return a;
}
__device__ __forceinline__ void ldsm4(uint32_t addr, uint32_t* r) {
    asm volatile("ldmatrix.sync.aligned.m8n8.x4.shared.b16 {%0,%1,%2,%3}, [%4];"
                 : "=r"(r[0]), "=r"(r[1]), "=r"(r[2]), "=r"(r[3]) : "r"(addr));
}
__device__ __forceinline__ void mma16816(float* c, const uint32_t* a, const uint32_t* b) {
    asm volatile(
        "mma.sync.aligned.m16n8k16.row.col.f32.bf16.bf16.f32 "
        "{%0,%1,%2,%3}, {%4,%5,%6,%7}, {%8,%9}, {%0,%1,%2,%3};"
        : "+f"(c[0]), "+f"(c[1]), "+f"(c[2]), "+f"(c[3])
        : "r"(a[0]), "r"(a[1]), "r"(a[2]), "r"(a[3]), "r"(b[0]), "r"(b[1]));
}
__device__ __forceinline__ void cpasync16(uint32_t dst, const void* src) {
    asm volatile("cp.async.cg.shared.global [%0], [%1], 16;" :: "r"(dst), "l"(src) : "memory");
}
#define CP_COMMIT() asm volatile("cp.async.commit_group;" ::: "memory")
#define CP_WAIT0()  asm volatile("cp.async.wait_group 0;" ::: "memory")

// ---------------------------------------------------------------------------
// Fused: a -> (hi, lo) split AND degree d = rsqrt(rowsum + 1 + 1e-8)
// ---------------------------------------------------------------------------
__global__ void __launch_bounds__(256) dsplit_a_kernel(const float* __restrict__ a) {
    int warp = (blockIdx.x * 256 + threadIdx.x) >> 5;
    int lane = threadIdx.x & 31;
    const float4* row = (const float4*)(a + (size_t)warp * NNODE);
    __nv_bfloat162* hi = (__nv_bfloat162*)(g_ahi + (size_t)warp * NNODE);
    __nv_bfloat162* lo = (__nv_bfloat162*)(g_alo + (size_t)warp * NNODE);
    float s = 0.f;
#pragma unroll
    for (int j = 0; j < 8; j++) {
        int i4 = lane + j * 32;
        float4 v = row[i4];
        s += v.x + v.y + v.z + v.w;
        float f[4] = {v.x, v.y, v.z, v.w};
        __nv_bfloat16 h[4], l[4];
#pragma unroll
        for (int k = 0; k < 4; k++) {
            h[k] = __float2bfloat16(f[k]);
            l[k] = __float2bfloat16(f[k] - __bfloat162float(h[k]));
        }
        hi[2 * i4]     = __nv_bfloat162(h[0], h[1]);
        hi[2 * i4 + 1] = __nv_bfloat162(h[2], h[3]);
        lo[2 * i4]     = __nv_bfloat162(l[0], l[1]);
        lo[2 * i4 + 1] = __nv_bfloat162(l[2], l[3]);
    }
#pragma unroll
    for (int off = 16; off; off >>= 1) s += __shfl_xor_sync(0xffffffffu, s, off);
    if (lane == 0) g_d[warp] = rsqrtf(s + 1.0f + 1e-8f);
}

// ---------------------------------------------------------------------------
// Kernel: xt[b,c,j] = d[b,j] * x[b,j,c]  transposed + split into hi/lo
// ---------------------------------------------------------------------------
__global__ void __launch_bounds__(256) split_xt_kernel(const float* __restrict__ x) {
    __shared__ float t[32][33];
    int b  = blockIdx.z;
    int j0 = blockIdx.y * 32;
    int c0 = blockIdx.x * 32;
    int tx = threadIdx.x, ty = threadIdx.y;      // (32, 8)
#pragma unroll
    for (int k = 0; k < 4; k++) {
        int j = j0 + ty + k * 8;
        float dv = g_d[b * NNODE + j];
        t[ty + k * 8][tx] = x[((size_t)(b * NNODE + j)) * IND + c0 + tx] * dv;
    }
    __syncthreads();
#pragma unroll
    for (int k = 0; k < 4; k++) {
        int c = c0 + ty + k * 8;
        int j = j0 + tx;
        float v = t[tx][ty + k * 8];
        __nv_bfloat16 h = __float2bfloat16(v);
        size_t o = ((size_t)b * IND + c) * NNODE + j;
        g_xthi[o] = h;
        g_xtlo[o] = __float2bfloat16(v - __bfloat162float(h));
    }
}

// ---------------------------------------------------------------------------
// All weight splits in one kernel
// ---------------------------------------------------------------------------
#define W1_F4   (HIDD * IND / 4)          // 131072
#define WHD_F4  (LATD * HIDD / 4)         // 65536
__global__ void __launch_bounds__(256) split_w_kernel(const float* __restrict__ W1,
                                                      const float* __restrict__ Wmu,
                                                      const float* __restrict__ Wlv) {
    size_t i = (size_t)blockIdx.x * 256 + threadIdx.x;
    const float* src; __nv_bfloat16 *hi, *lo; size_t o;
    if (i < W1_F4)                 { src = W1;  hi = g_w1hi;  lo = g_w1lo;  o = i; }
    else if (i < W1_F4 + WHD_F4)   { src = Wmu; hi = g_wcathi; lo = g_wcatlo; o = i - W1_F4; }
    else                           { src = Wlv; hi = g_wcathi + (size_t)LATD * HIDD;
                                     lo = g_wcatlo + (size_t)LATD * HIDD; o = i - W1_F4 - WHD_F4; }
    float4 v = ((const float4*)src)[o];
    float f[4] = {v.x, v.y, v.z, v.w};
    __nv_bfloat16 h[4], l[4];
#pragma unroll
    for (int k = 0; k < 4; k++) {
        h[k] = __float2bfloat16(f[k]);
        l[k] = __float2bfloat16(f[k] - __bfloat162float(h[k]));
    }
    ((__nv_bfloat162*)hi)[2 * o]     = __nv_bfloat162(h[0], h[1]);
    ((__nv_bfloat162*)hi)[2 * o + 1] = __nv_bfloat162(h[2], h[3]);
    ((__nv_bfloat162*)lo)[2 * o]     = __nv_bfloat162(l[0], l[1]);
    ((__nv_bfloat162*)lo)[2 * o + 1] = __nv_bfloat162(l[2], l[3]);
}

// ---------------------------------------------------------------------------
// Split-bf16 GEMM via mma.sync (HMMA): D[m,n] = sum_k A[m,k]*B[n,k]
//   3-term compensation: Ahi*Bhi + Ahi*Blo + Alo*Bhi  (fp32-equivalent)
// Inner loop is TERM-MAJOR: dependent MMAs on one accumulator are 4 apart.
// ---------------------------------------------------------------------------
#define TILE_B 10240        // 128 rows * 80B
#define BUF_B  40960        // 4 tiles
#define GEMM_SMEM 81920     // 2 buffers
#define STG_STRIDE 272      // bytes: (128+8) bf16 per row

template <int KDIM, int EPI, int LDO>
__global__ void __launch_bounds__(256, 2) gemm_k(
    const __nv_bfloat16* __restrict__ Ahi, const __nv_bfloat16* __restrict__ Alo,
    const __nv_bfloat16* __restrict__ Bhi, const __nv_bfloat16* __restrict__ Blo,
    long bstride,
    float* __restrict__ outf,
    __nv_bfloat16* __restrict__ ohi, __nv_bfloat16* __restrict__ olo,
    const float* __restrict__ bias, const float* __restrict__ bias2,
    const float* __restrict__ xdiag)
{
    extern __shared__ char smem_raw[];
    const uint32_t sb  = smem_u32(smem_raw);
    const int tid  = threadIdx.x;
    const int wid  = tid >> 5;
    const int lane = tid & 31;
    const int n0   = blockIdx.x * 128;
    const int m0   = blockIdx.y * 128;
    const int wm   = wid & 3;
    const int wn   = wid >> 2;

    const long batch = bstride ? (long)(m0 >> 10) : 0;
    const __nv_bfloat16* srcs[4] = {Ahi, Alo, Bhi + batch * bstride, Blo + batch * bstride};

    float acc[2][8][4];
#pragma unroll
    for (int i = 0; i < 2; i++)
#pragma unroll
        for (int j = 0; j < 8; j++)
#pragma unroll
            for (int k = 0; k < 4; k++) acc[i][j][k] = 0.f;

    const int srow = tid >> 2;
    const int sc4  = tid & 3;

    size_t gsrc[4];
#pragma unroll
    for (int tile = 0; tile < 4; tile++) {
        const int rbase = (tile < 2) ? m0 : n0;
        gsrc[tile] = (size_t)(rbase + srow) * KDIM + sc4 * 8;
    }

    const uint32_t a_roff = (uint32_t)((wm * 32 + (lane & 15)) * 80 + ((lane >> 4) * 8) * 2);
    const uint32_t b_roff = (uint32_t)((wn * 64 + ((lane >> 4) << 3) + (lane & 7)) * 80
                                       + (((lane >> 3) & 1) * 8) * 2);

    const int NC = KDIM / 32;

#pragma unroll
    for (int tile = 0; tile < 4; tile++)
#pragma unroll
        for (int rep = 0; rep < 2; rep++)
            cpasync16(sb + tile * TILE_B + (srow + rep * 64) * 80 + sc4 * 16,
                      srcs[tile] + gsrc[tile] + (size_t)rep * 64 * KDIM);
    CP_COMMIT();

    for (int t = 0; t < NC; t++) {
        CP_WAIT0();
        __syncthreads();

        if (t + 1 < NC) {
            const int kk = (t + 1) * 32;
            const uint32_t nb = sb + (uint32_t)((t + 1) & 1) * BUF_B;
#pragma unroll
            for (int tile = 0; tile < 4; tile++)
#pragma unroll
                for (int rep = 0; rep < 2; rep++)
                    cpasync16(nb + tile * TILE_B + (srow + rep * 64) * 80 + sc4 * 16,
                              srcs[tile] + gsrc[tile] + (size_t)rep * 64 * KDIM + kk);
            CP_COMMIT();
        }

        const uint32_t base = sb + (uint32_t)(t & 1) * BUF_B;
#pragma unroll
        for (int ks = 0; ks < 2; ks++) {
            const uint32_t koff = ks * 32;
            uint32_t ah[2][4], al[2][4];
#pragma unroll
            for (int tm = 0; tm < 2; tm++) {
                ldsm4(base + 0 * TILE_B + a_roff + tm * (16 * 80) + koff, ah[tm]);
                ldsm4(base + 1 * TILE_B + a_roff + tm * (16 * 80) + koff, al[tm]);
            }
#pragma unroll
            for (int tnp = 0; tnp < 4; tnp++) {
                uint32_t bh[4], bl[4];
                ldsm4(base + 2 * TILE_B + b_roff + tnp * (16 * 80) + koff, bh);
                ldsm4(base + 3 * TILE_B + b_roff + tnp * (16 * 80) + koff, bl);
                // TERM-MAJOR ordering: 4 independent accumulators per term,
                // dependent MMAs on the same acc are 4 issue slots apart.
#pragma unroll
                for (int tm = 0; tm < 2; tm++)
#pragma unroll
                    for (int hf = 0; hf < 2; hf++)
                        mma16816(acc[tm][tnp * 2 + hf], ah[tm], bh + hf * 2);
#pragma unroll
                for (int tm = 0; tm < 2; tm++)
#pragma unroll
                    for (int hf = 0; hf < 2; hf++)
                        mma16816(acc[tm][tnp * 2 + hf], ah[tm], bl + hf * 2);
#pragma unroll
                for (int tm = 0; tm < 2; tm++)
#pragma unroll
                    for (int hf = 0; hf < 2; hf++)
                        mma16816(acc[tm][tnp * 2 + hf], al[tm], bh + hf * 2);
            }
        }
    }

    if (EPI == 3) {
#pragma unroll
        for (int tm = 0; tm < 2; tm++)
#pragma unroll
            for (int hf = 0; hf < 2; hf++) {
                const int row = m0 + wm * 32 + tm * 16 + hf * 8 + (lane >> 2);
#pragma unroll
                for (int tn = 0; tn < 8; tn++) {
                    const int col = n0 + wn * 64 + tn * 8 + (lane & 3) * 2;
                    float v0 = acc[tm][tn][hf * 2 + 0];
                    float v1 = acc[tm][tn][hf * 2 + 1];
                    const float* bp = (col < LATD) ? (bias + col) : (bias2 + col - LATD);
                    float2 bv = *(const float2*)bp;
                    v0 += bv.x; v1 += bv.y;
                    float* dst = (col < LATD)
                        ? (outf + (size_t)row * LATD + col)
                        : (outf + (size_t)TOK * LATD + (size_t)row * LATD + (col - LATD));
                    *(float2*)dst = make_float2(v0, v1);
                }
            }
        return;
    }

    // EPI 0/1: epilogue math, SMEM restage, 16B/lane global stores
    __syncthreads();
    char* hi_st = smem_raw;
    char* lo_st = smem_raw + 40960;
#pragma unroll
    for (int tm = 0; tm < 2; tm++) {
#pragma unroll
        for (int hf = 0; hf < 2; hf++) {
            const int rl = wm * 32 + tm * 16 + hf * 8 + (lane >> 2);
            const int row = m0 + rl;
            float di = 0.f, d2 = 0.f;
            if (EPI == 0) { di = g_d[row]; d2 = di * di; }
#pragma unroll
            for (int tn = 0; tn < 8; tn++) {
                const int cl = wn * 64 + tn * 8 + (lane & 3) * 2;
                float v0 = acc[tm][tn][hf * 2 + 0];
                float v1 = acc[tm][tn][hf * 2 + 1];
                if (EPI == 0) {
                    float2 xv = *(const float2*)(xdiag + (size_t)row * LDO + n0 + cl);
                    v0 = di * v0 + d2 * xv.x;
                    v1 = di * v1 + d2 * xv.y;
                } else {
                    float2 bv = *(const float2*)(bias + n0 + cl);
                    v0 = fmaxf(v0 + bv.x, 0.f);
                    v1 = fmaxf(v1 + bv.y, 0.f);
                }
                __nv_bfloat16 h0 = __float2bfloat16(v0);
                __nv_bfloat16 h1 = __float2bfloat16(v1);
                *(__nv_bfloat162*)(hi_st + rl * STG_STRIDE + cl * 2) = __nv_bfloat162(h0, h1);
                *(__nv_bfloat162*)(lo_st + rl * STG_STRIDE + cl * 2) = __nv_bfloat162(
                    __float2bfloat16(v0 - __bfloat162float(h0)),
                    __float2bfloat16(v1 - __bfloat162float(h1)));
            }
        }
    }
    __syncthreads();
#pragma unroll
    for (int it = 0; it < 8; it++) {
        int lin = it * 256 + tid;
        int r   = lin >> 4;
        int c16 = lin & 15;
        uint4 vh = *(uint4*)(hi_st + r * STG_STRIDE + c16 * 16);
        uint4 vl = *(uint4*)(lo_st + r * STG_STRIDE + c16 * 16);
        size_t go = (size_t)(m0 + r) * LDO + n0 + c16 * 8;
        *(uint4*)(ohi + go) = vh;
        *(uint4*)(olo + go) = vl;
    }
}

// ---------------------------------------------------------------------------
extern "C" void kernel_launch(void* const* d_in, const int* in_sizes, int n_in,
                              void* d_out, int out_size) {
    const float* x   = (const float*)d_in[0];
    const float* a   = (const float*)d_in[1];
    const float* W1  = (const float*)d_in[2];
    const float* b1  = (const float*)d_in[3];
    const float* Wmu = (const float*)d_in[4];
    const float* bmu = (const float*)d_in[5];
    const float* Wlv = (const float*)d_in[6];
    const float* blv = (const float*)d_in[7];
    float* out = (float*)d_out;

    cudaFuncSetAttribute(gemm_k<NNODE, 0, IND>,  cudaFuncAttributeMaxDynamicSharedMemorySize, GEMM_SMEM);
    cudaFuncSetAttribute(gemm_k<IND,   1, HIDD>, cudaFuncAttributeMaxDynamicSharedMemorySize, GEMM_SMEM);
    cudaFuncSetAttribute(gemm_k<HIDD,  3, LATD>, cudaFuncAttributeMaxDynamicSharedMemorySize, GEMM_SMEM);

    __nv_bfloat16 *ahi, *alo, *xthi, *xtlo, *hhi, *hlo, *h1hi, *h1lo;
    __nv_bfloat16 *w1hi, *w1lo, *wchi, *wclo;
    cudaGetSymbolAddress((void**)&ahi,  g_ahi);  cudaGetSymbolAddress((void**)&alo,  g_alo);
    cudaGetSymbolAddress((void**)&xthi, g_xthi); cudaGetSymbolAddress((void**)&xtlo, g_xtlo);
    cudaGetSymbolAddress((void**)&hhi,  g_hhi);  cudaGetSymbolAddress((void**)&hlo,  g_hlo);
    cudaGetSymbolAddress((void**)&h1hi, g_h1hi); cudaGetSymbolAddress((void**)&h1lo, g_h1lo);
    cudaGetSymbolAddress((void**)&w1hi, g_w1hi); cudaGetSymbolAddress((void**)&w1lo, g_w1lo);
    cudaGetSymbolAddress((void**)&wchi, g_wcathi); cudaGetSymbolAddress((void**)&wclo, g_wcatlo);

    // #1 fused adjacency split + degree factors
    dsplit_a_kernel<<<TOK / 8, 256>>>(a);
    // #2 x transpose + d_j scale + split
    split_xt_kernel<<<dim3(IND / 32, NNODE / 32, BB), dim3(32, 8)>>>(x);
    // #3 all weight splits
    split_w_kernel<<<(W1_F4 + 2 * WHD_F4) / 256, 256>>>(W1, Wmu, Wlv);
    // #4 message passing GEMM (profiled launch)
    gemm_k<NNODE, 0, IND><<<dim3(IND / 128, TOK / 128), 256, GEMM_SMEM>>>(
        ahi, alo, xthi, xtlo, (long)IND * NNODE, nullptr, hhi, hlo, nullptr, nullptr, x);
    // #5 h1 = relu(h @ W1^T + b1)
    gemm_k<IND, 1, HIDD><<<dim3(HIDD / 128, TOK / 128), 256, GEMM_SMEM>>>(
        hhi, hlo, w1hi, w1lo, 0, nullptr, h1hi, h1lo, b1, nullptr, nullptr);
    // #6 fused mu+logvar heads: one N=512 GEMM over [Wmu; Wlv]
    gemm_k<HIDD, 3, LATD><<<dim3((2 * LATD) / 128, TOK / 128), 256, GEMM_SMEM>>>(
        h1hi, h1lo, wchi, wclo, 0, out, nullptr, nullptr, bmu, blv, nullptr);
}